// round 13
// baseline (speedup 1.0000x reference)
#include <cuda_runtime.h>
#include <cstdint>

#define NB 8
#define SQ 2048
#define SK 2048
#define DD 512
#define DV 512
#define LDW 512       // all matrices have 512-float rows
#define KSPLIT 4      // split-K factor for kernel A

// Tile geometry (raw fp32 tiles, split to tf32 at fragment load)
//   TRANS=1 : tile layout [k:32][x:128], row stride 136 floats (136%32==8 -> conflict-free frags)
//   TRANS=0 : tile layout [m:128][k:32], row stride 36 floats  ( 36%32==4 -> conflict-free frags)
#define S1 136
#define S0 36
#define TSF1 (32 * S1)    // floats per tile, TRANS=1 (4352)
#define TSF0 (128 * S0)   // floats per tile, TRANS=0 (4608)
#define GEMM_SMEM (2 * 2 * TSF0 * 4)   // max(T0,T1) buffers: 73728 bytes

__device__ float g_P [KSPLIT * NB * DV * DD];  // split-K partials for MT
__device__ float g_MT[NB * DV * DD];           // MT[b][v][d] = sum_s V[s,v]*K[s,d]
__device__ float g_X [NB * SQ * DV];           // X[b][q][v] = (Q @ MT^T)/sqrt(512)
__device__ int   g_vl[SQ];

// ---------------------------------------------------------------------------
// helpers
// ---------------------------------------------------------------------------
__device__ __forceinline__ uint32_t smem_u32(const void* p) {
    uint32_t a;
    asm("{ .reg .u64 t; cvta.to.shared.u64 t, %1; cvt.u32.u64 %0, t; }" : "=r"(a) : "l"(p));
    return a;
}
__device__ __forceinline__ void split2(float x, uint32_t& h, uint32_t& l) {
    asm("cvt.rna.tf32.f32 %0, %1;" : "=r"(h) : "f"(x));
    float r = x - __uint_as_float(h);
    asm("cvt.rna.tf32.f32 %0, %1;" : "=r"(l) : "f"(r));
}

#define CP16(sa, gp) asm volatile( \
    "cp.async.cg.shared.global [%0], [%1], 16;" :: "r"(sa), "l"(gp))
#define CP_COMMIT() asm volatile("cp.async.commit_group;" ::: "memory")
#define CP_WAIT1()  asm volatile("cp.async.wait_group 1;" ::: "memory")

// D += A * B^T : m16n8k8 tf32 (A row-major 16x8, B [n][k])
#define MMA(c, a, b) asm volatile( \
    "mma.sync.aligned.m16n8k8.row.col.f32.tf32.tf32.f32 " \
    "{%0,%1,%2,%3}, {%4,%5,%6,%7}, {%8,%9}, {%0,%1,%2,%3};" \
    : "+f"((c)[0]), "+f"((c)[1]), "+f"((c)[2]), "+f"((c)[3]) \
    : "r"((a)[0]), "r"((a)[1]), "r"((a)[2]), "r"((a)[3]), \
      "r"((b)[0]), "r"((b)[1]))

// ---------------------------------------------------------------------------
// Kernel 0: normalize valid_len (autodetect int64 vs int32 buffer layout)
// ---------------------------------------------------------------------------
__global__ void normalize_vlen_kernel(const int* __restrict__ raw)
{
    __shared__ int odd_nonzero;
    if (threadIdx.x == 0) odd_nonzero = 0;
    __syncthreads();
    int local = 0;
    for (int i = threadIdx.x; i < SQ; i += blockDim.x)
        if ((i & 1) && raw[i] != 0) local = 1;
    if (local) atomicOr(&odd_nonzero, 1);
    __syncthreads();
    const bool is32 = (odd_nonzero != 0);
    for (int q = threadIdx.x; q < SQ; q += blockDim.x)
        g_vl[q] = is32 ? raw[q] : raw[2 * q];
}

// ---------------------------------------------------------------------------
// Split-K reduce: g_MT = sum over KSPLIT partials (deterministic order)
// ---------------------------------------------------------------------------
__global__ __launch_bounds__(256) void reduce_mt_kernel()
{
    const int idx = blockIdx.x * blockDim.x + threadIdx.x;   // float4 index
    const float4* p0 = (const float4*)g_P + idx;
    const size_t stride4 = (size_t)NB * DV * DD / 4;
    float4 a = p0[0], b = p0[stride4], c = p0[2 * stride4], d = p0[3 * stride4];
    float4 r;
    r.x = (a.x + b.x) + (c.x + d.x);
    r.y = (a.y + b.y) + (c.y + d.y);
    r.z = (a.z + b.z) + (c.z + d.z);
    r.w = (a.w + b.w) + (c.w + d.w);
    ((float4*)g_MT)[idx] = r;
}

// ---------------------------------------------------------------------------
// tf32x3 GEMM, cp.async double-buffered, split-at-fragment-load.
//   TRANS=1 (kernel A): A'=V^T, B'=K^T (gmem [k][x]); split-K x4 partials.
//   TRANS=0 (kernel B): A'=Q,   B'=MT  (gmem [x][k]); C = X * (1/sqrt(512)).
// 8 warps as 2(m) x 4(n); warp tile 64x32 = 4x4 m16n8k8 atoms; k-chunk 32.
// ---------------------------------------------------------------------------
template <int TRANS>
__global__ __launch_bounds__(256, 2) void gemm_cp(
    const float* __restrict__ p0, const float* __restrict__ p1)
{
    extern __shared__ float smf[];
    const int TSF = TRANS ? TSF1 : TSF0;
    const uint32_t sb0 = smem_u32(smf);

    const int tid = threadIdx.x, lane = tid & 31, wid = tid >> 5;
    const int wm = wid >> 2, wn = wid & 3;         // warp grid 2 x 4
    const int fg = lane >> 2, ft = lane & 3;       // frag group / k-offset
    const int n0 = blockIdx.x * 128, m0 = blockIdx.y * 128;

    const float* __restrict__ Ag;
    const float* __restrict__ Bg;
    float* __restrict__ Cb;
    int nch; float csc;
    if (TRANS) {   // A=V [s][v], B=K [s][d], C partial -> g_P[seg][b]
        const int b = blockIdx.z >> 2, seg = blockIdx.z & 3;
        const size_t soff = (size_t)seg * (SK / KSPLIT) * LDW;
        Ag = p0 + (size_t)b * SK * DV + soff;
        Bg = p1 + (size_t)b * SK * DD + soff;
        Cb = g_P + ((size_t)seg * NB + b) * DV * DD;
        nch = (SK / KSPLIT) / 32;  csc = 1.0f;
    } else {       // A=Q [q][d], B=g_MT [v][d], C=g_X [q][v]
        const int b = blockIdx.z;
        Ag = p0 + (size_t)b * SQ * DD;
        Bg = g_MT + (size_t)b * DV * DD;
        Cb = g_X + (size_t)b * SQ * DV;
        nch = DD / 32;  csc = 0.044194173824159216f;
    }

    // issue async copy of one chunk into buffer `buf`
    auto copy_chunk = [&](int ch, int buf) {
        const int k0 = ch * 32;
        const uint32_t sbA = sb0 + (uint32_t)(buf * 2 * TSF) * 4;
        const uint32_t sbB = sbA + (uint32_t)TSF * 4;
        if (TRANS) {
            // tile [k:32][x:128], row stride S1; 1024 16B-segs per tile
#pragma unroll
            for (int i = 0; i < 4; i++) {
                const int s = tid + i * 256;
                const int row = s >> 5, c16 = s & 31;
                CP16(sbA + (uint32_t)(row * S1 + c16 * 4) * 4,
                     Ag + (size_t)(k0 + row) * LDW + m0 + c16 * 4);
                CP16(sbB + (uint32_t)(row * S1 + c16 * 4) * 4,
                     Bg + (size_t)(k0 + row) * LDW + n0 + c16 * 4);
            }
        } else {
            // tile [m:128][k:32], row stride S0; 1024 16B-segs per tile
#pragma unroll
            for (int i = 0; i < 4; i++) {
                const int s = tid + i * 256;
                const int row = s >> 3, c16 = s & 7;
                CP16(sbA + (uint32_t)(row * S0 + c16 * 4) * 4,
                     Ag + (size_t)(m0 + row) * LDW + k0 + c16 * 4);
                CP16(sbB + (uint32_t)(row * S0 + c16 * 4) * 4,
                     Bg + (size_t)(n0 + row) * LDW + k0 + c16 * 4);
            }
        }
    };

    float c[4][4][4];
#pragma unroll
    for (int i = 0; i < 4; i++)
#pragma unroll
        for (int j = 0; j < 4; j++)
#pragma unroll
            for (int u = 0; u < 4; u++) c[i][j][u] = 0.0f;

    // prologue: stage chunks 0 and 1
    copy_chunk(0, 0); CP_COMMIT();
    copy_chunk(1, 1); CP_COMMIT();

    for (int ch = 0; ch < nch; ch++) {
        CP_WAIT1();              // this thread's copies for buf[ch&1] complete
        __syncthreads();         // -> visible to all threads

        const float* TA = smf + (size_t)(ch & 1) * 2 * TSF;
        const float* TB = TA + TSF;

        // ---- MMA: 4 k-steps of 8, tf32x3, split at fragment load ----
#pragma unroll
        for (int ks = 0; ks < 4; ks++) {
            const int kk = ks * 8;

            uint32_t bh[4][2], bl[4][2];
#pragma unroll
            for (int an = 0; an < 4; an++) {
                const int nr = wn * 32 + an * 8 + fg;
                float r0, r1;
                if (TRANS) {
                    r0 = TB[(size_t)(kk + ft) * S1 + nr];
                    r1 = TB[(size_t)(kk + ft + 4) * S1 + nr];
                } else {
                    r0 = TB[(size_t)nr * S0 + kk + ft];
                    r1 = TB[(size_t)nr * S0 + kk + ft + 4];
                }
                split2(r0, bh[an][0], bl[an][0]);
                split2(r1, bh[an][1], bl[an][1]);
            }
#pragma unroll
            for (int am = 0; am < 4; am++) {
                const int mr = wm * 64 + am * 16 + fg;
                float r0, r1, r2, r3;
                if (TRANS) {
                    r0 = TA[(size_t)(kk + ft) * S1 + mr];
                    r1 = TA[(size_t)(kk + ft) * S1 + mr + 8];
                    r2 = TA[(size_t)(kk + ft + 4) * S1 + mr];
                    r3 = TA[(size_t)(kk + ft + 4) * S1 + mr + 8];
                } else {
                    r0 = TA[(size_t)mr * S0 + kk + ft];
                    r1 = TA[(size_t)(mr + 8) * S0 + kk + ft];
                    r2 = TA[(size_t)mr * S0 + kk + ft + 4];
                    r3 = TA[(size_t)(mr + 8) * S0 + kk + ft + 4];
                }
                uint32_t ah[4], al[4];
                split2(r0, ah[0], al[0]);
                split2(r1, ah[1], al[1]);
                split2(r2, ah[2], al[2]);
                split2(r3, ah[3], al[3]);
#pragma unroll
                for (int an = 0; an < 4; an++) MMA(c[am][an], ah, bh[an]);
#pragma unroll
                for (int an = 0; an < 4; an++) MMA(c[am][an], al, bh[an]);
#pragma unroll
                for (int an = 0; an < 4; an++) MMA(c[am][an], ah, bl[an]);
            }
        }

        __syncthreads();         // all warps done reading buf[ch&1]
        if (ch + 2 < nch) copy_chunk(ch + 2, ch & 1);
        CP_COMMIT();             // commit (possibly empty) group each iteration
    }

    // ---- epilogue ----
#pragma unroll
    for (int am = 0; am < 4; am++) {
        const int mr = m0 + wm * 64 + am * 16 + fg;
#pragma unroll
        for (int an = 0; an < 4; an++) {
            const int nc = n0 + wn * 32 + an * 8 + ft * 2;
            float2 w0 = make_float2(c[am][an][0] * csc, c[am][an][1] * csc);
            float2 w1 = make_float2(c[am][an][2] * csc, c[am][an][3] * csc);
            *(float2*)&Cb[(size_t)mr * LDW + nc]       = w0;
            *(float2*)&Cb[(size_t)(mr + 8) * LDW + nc] = w1;
        }
    }
}

// ---------------------------------------------------------------------------
// Kernel C: mask (col > valid_len[q] -> -1e6) + row softmax over 512 cols.
// ---------------------------------------------------------------------------
__global__ __launch_bounds__(256) void softmax_kernel(float* __restrict__ out)
{
    const int b = blockIdx.y, q0 = blockIdx.x * 32;
    const int tid = threadIdx.x, lane = tid & 31, warp = tid >> 5;
    const int r0 = warp * 4;
    const float* __restrict__ Xb = g_X + (size_t)b * SQ * DV;

    float acc[4][16];
#pragma unroll
    for (int i = 0; i < 4; i++) {
        const float* row = Xb + (size_t)(q0 + r0 + i) * DV;
#pragma unroll
        for (int j = 0; j < 16; j++) acc[i][j] = row[lane + 32 * j];
    }

#pragma unroll
    for (int i = 0; i < 4; i++) {
        const int q = q0 + r0 + i;
        const int vl = g_vl[q];
        float rmax = -3.402823e38f;
#pragma unroll
        for (int j = 0; j < 16; j++) {
            const int cidx = lane + 32 * j;
            float x = acc[i][j];
            if (cidx > vl) x = -1000000.0f;
            acc[i][j] = x;
            rmax = fmaxf(rmax, x);
        }
#pragma unroll
        for (int off = 16; off > 0; off >>= 1)
            rmax = fmaxf(rmax, __shfl_xor_sync(0xFFFFFFFFu, rmax, off));
        float rsum = 0.0f;
#pragma unroll
        for (int j = 0; j < 16; j++) {
            const float e = __expf(acc[i][j] - rmax);
            acc[i][j] = e;
            rsum += e;
        }
#pragma unroll
        for (int off = 16; off > 0; off >>= 1)
            rsum += __shfl_xor_sync(0xFFFFFFFFu, rsum, off);
        const float inv = 1.0f / rsum;
        float* __restrict__ orow = out + (size_t)b * SQ * DV + (size_t)q * DV;
#pragma unroll
        for (int j = 0; j < 16; j++)
            orow[lane + 32 * j] = acc[i][j] * inv;
    }
}

extern "C" void kernel_launch(void* const* d_in, const int* in_sizes, int n_in,
                              void* d_out, int out_size)
{
    const float* K   = (const float*)d_in[0];
    const float* V   = (const float*)d_in[1];
    const float* Q   = (const float*)d_in[2];
    const int*   vlr = (const int*)d_in[3];
    float*       out = (float*)d_out;

    cudaFuncSetAttribute(gemm_cp<1>, cudaFuncAttributeMaxDynamicSharedMemorySize, GEMM_SMEM);
    cudaFuncSetAttribute(gemm_cp<0>, cudaFuncAttributeMaxDynamicSharedMemorySize, GEMM_SMEM);

    normalize_vlen_kernel<<<1, 1024>>>(vlr);

    dim3 gA(DD / 128, DV / 128, NB * KSPLIT);        // (4, 4, 32): partials
    gemm_cp<1><<<gA, 256, GEMM_SMEM>>>(V, K);

    reduce_mt_kernel<<<(NB * DV * DD / 4) / 256, 256>>>();   // 2048 blocks

    dim3 gB(DV / 128, SQ / 128, NB);                 // (4, 16, 8): X[q][v]
    gemm_cp<0><<<gB, 256, GEMM_SMEM>>>(Q, nullptr);

    dim3 gC(SQ / 32, NB);                            // (64, 8)
    softmax_kernel<<<gC, 256>>>(out);
}

// round 15
// speedup vs baseline: 1.4778x; 1.4778x over previous
#include <cuda_runtime.h>
#include <cstdint>

#define NB 8
#define SQ 2048
#define SK 2048
#define DD 512
#define DV 512
#define LDW 512       // all matrices have 512-float rows
#define KSPLIT 4      // split-K factor for kernel A
#define KC 16         // k-chunk
#define TS 20         // tile row stride in floats ((20*fg+ft)%32 distinct -> conflict-free)
#define TILEF (128 * TS)            // floats per tile (2560)
#define BUFF  (4 * TILEF)           // floats per buffer: Ah,Al,Bh,Bl (10240)
#define GEMM_SMEM (2 * BUFF * 4)    // 81920 bytes

__device__ float g_P [KSPLIT * NB * DV * DD];  // split-K partials for MT
__device__ float g_MT[NB * DV * DD];           // MT[b][v][d] = sum_s V[s,v]*K[s,d]
__device__ float g_X [NB * SQ * DV];           // X[b][q][v] = (Q @ MT^T)/sqrt(512)
__device__ int   g_vl[SQ];

// ---------------------------------------------------------------------------
// helpers
// ---------------------------------------------------------------------------
__device__ __forceinline__ void split2(float x, uint32_t& h, uint32_t& l) {
    asm("cvt.rna.tf32.f32 %0, %1;" : "=r"(h) : "f"(x));
    float r = x - __uint_as_float(h);
    asm("cvt.rna.tf32.f32 %0, %1;" : "=r"(l) : "f"(r));
}
__device__ __forceinline__ void split4(float4 g, uint4& h, uint4& l) {
    split2(g.x, h.x, l.x); split2(g.y, h.y, l.y);
    split2(g.z, h.z, l.z); split2(g.w, h.w, l.w);
}

// D += A * B^T : m16n8k8 tf32 (A row-major 16x8, B [n][k])
#define MMA(c, a, b) asm volatile( \
    "mma.sync.aligned.m16n8k8.row.col.f32.tf32.tf32.f32 " \
    "{%0,%1,%2,%3}, {%4,%5,%6,%7}, {%8,%9}, {%0,%1,%2,%3};" \
    : "+f"((c)[0]), "+f"((c)[1]), "+f"((c)[2]), "+f"((c)[3]) \
    : "r"((a)[0]), "r"((a)[1]), "r"((a)[2]), "r"((a)[3]), \
      "r"((b)[0]), "r"((b)[1]))

__device__ __forceinline__ void ldfragA(const float* T, int r0, int kk, int lane,
                                        uint32_t a[4]) {
    const float* p = T + (size_t)(r0 + (lane >> 2)) * TS + kk + (lane & 3);
    a[0] = __float_as_uint(p[0]);
    a[1] = __float_as_uint(p[8 * TS]);
    a[2] = __float_as_uint(p[4]);
    a[3] = __float_as_uint(p[8 * TS + 4]);
}
__device__ __forceinline__ void ldfragB(const float* T, int n0, int kk, int lane,
                                        uint32_t b[2]) {
    const float* p = T + (size_t)(n0 + (lane >> 2)) * TS + kk + (lane & 3);
    b[0] = __float_as_uint(p[0]);
    b[1] = __float_as_uint(p[4]);
}

// ---------------------------------------------------------------------------
// Kernel 0: normalize valid_len (autodetect int64 vs int32 buffer layout)
// ---------------------------------------------------------------------------
__global__ void normalize_vlen_kernel(const int* __restrict__ raw)
{
    __shared__ int odd_nonzero;
    if (threadIdx.x == 0) odd_nonzero = 0;
    __syncthreads();
    int local = 0;
    for (int i = threadIdx.x; i < SQ; i += blockDim.x)
        if ((i & 1) && raw[i] != 0) local = 1;
    if (local) atomicOr(&odd_nonzero, 1);
    __syncthreads();
    const bool is32 = (odd_nonzero != 0);
    for (int q = threadIdx.x; q < SQ; q += blockDim.x)
        g_vl[q] = is32 ? raw[q] : raw[2 * q];
}

// ---------------------------------------------------------------------------
// Split-K reduce: g_MT = sum over KSPLIT partials (deterministic order)
// ---------------------------------------------------------------------------
__global__ __launch_bounds__(256) void reduce_mt_kernel()
{
    const int idx = blockIdx.x * blockDim.x + threadIdx.x;   // float4 index
    const float4* p0 = (const float4*)g_P + idx;
    const size_t stride4 = (size_t)NB * DV * DD / 4;
    float4 a = p0[0], b = p0[stride4], c = p0[2 * stride4], d = p0[3 * stride4];
    float4 r;
    r.x = (a.x + b.x) + (c.x + d.x);
    r.y = (a.y + b.y) + (c.y + d.y);
    r.z = (a.z + b.z) + (c.z + d.z);
    r.w = (a.w + b.w) + (c.w + d.w);
    ((float4*)g_MT)[idx] = r;
}

// ---------------------------------------------------------------------------
// tf32x3 GEMM via mma.sync. k-chunk 16, DOUBLE-BUFFERED hi/lo tiles:
//   per chunk: LDG(c+1) -> sync -> MMA(c) -> split+STS(c+1) into other buffer.
//   One barrier per chunk; split happens once per element (R11 placement).
//   TRANS=1 (kernel A): A'=V^T, B'=K^T (gmem [k][x]); split-K x4 partials.
//                       Copy: threads 0-127 transpose A, 128-255 transpose B.
//   TRANS=0 (kernel B): A'=Q, B'=MT (gmem [x][k]); C = X * (1/sqrt(512)).
// 8 warps as 2(m) x 4(n); warp tile 64x32 = 4x4 m16n8k8 atoms.
// ---------------------------------------------------------------------------
template <int TRANS>
__global__ __launch_bounds__(256, 2) void gemm_mma(
    const float* __restrict__ p0, const float* __restrict__ p1)
{
    extern __shared__ float smf[];

    const int tid = threadIdx.x, lane = tid & 31, wid = tid >> 5;
    const int wm = wid >> 2, wn = wid & 3;       // warp grid 2 x 4
    const int n0 = blockIdx.x * 128, m0 = blockIdx.y * 128;

    const float* __restrict__ Ag;
    const float* __restrict__ Bg;
    float* __restrict__ Cb;
    int nch; float csc;
    if (TRANS) {   // A=V [s][v], B=K [s][d], C partial -> g_P[seg][b]
        const int b = blockIdx.z >> 2, seg = blockIdx.z & 3;
        const size_t soff = (size_t)seg * (SK / KSPLIT) * LDW;
        Ag = p0 + (size_t)b * SK * DV + soff;
        Bg = p1 + (size_t)b * SK * DD + soff;
        Cb = g_P + ((size_t)seg * NB + b) * DV * DD;
        nch = (SK / KSPLIT) / KC;  csc = 1.0f;
    } else {       // A=Q [q][d], B=g_MT [v][d], C=g_X [q][v]
        const int b = blockIdx.z;
        Ag = p0 + (size_t)b * SQ * DD;
        Bg = g_MT + (size_t)b * DV * DD;
        Cb = g_X + (size_t)b * SQ * DV;
        nch = DD / KC;  csc = 0.044194173824159216f;
    }

    // ---- copy helpers: LDG chunk into regs; split+STS regs into buffer ----
    auto ldg_chunk = [&](int ch, float4 g[4]) {
        const int k0 = ch * KC;
        if (TRANS) {
            const int w = tid & 127;
            const int s0 = 4 * (w & 3), x0 = 4 * (w >> 2);
            const float* __restrict__ P = (tid < 128) ? Ag : Bg;
            const int r0 = (tid < 128) ? m0 : n0;
#pragma unroll
            for (int i = 0; i < 4; i++)
                g[i] = *(const float4*)&P[(size_t)(k0 + s0 + i) * LDW + r0 + x0];
        } else {
#pragma unroll
            for (int i = 0; i < 2; i++) {
                const int f = tid + i * 256;       // 512 float4 per operand
                const int row = f >> 2, c4 = f & 3;
                g[i]     = *(const float4*)&Ag[(size_t)(m0 + row) * LDW + k0 + c4 * 4];
                g[2 + i] = *(const float4*)&Bg[(size_t)(n0 + row) * LDW + k0 + c4 * 4];
            }
        }
    };
    auto sts_chunk = [&](const float4 g[4], int buf) {
        float* base = smf + buf * BUFF;
        if (TRANS) {
            const int w = tid & 127;
            const int s0 = 4 * (w & 3), x0 = 4 * (w >> 2);
            float* Th = base + ((tid < 128) ? 0 : 2 * TILEF);
            float* Tl = Th + TILEF;
            const float* fa = (const float*)g;
#pragma unroll
            for (int j = 0; j < 4; j++) {
                float4 col = make_float4(fa[j], fa[4 + j], fa[8 + j], fa[12 + j]);
                uint4 h, l; split4(col, h, l);
                *(uint4*)&Th[(size_t)(x0 + j) * TS + s0] = h;
                *(uint4*)&Tl[(size_t)(x0 + j) * TS + s0] = l;
            }
        } else {
            float* Ah = base;
            float* Al = base + TILEF;
            float* Bh = base + 2 * TILEF;
            float* Bl = base + 3 * TILEF;
#pragma unroll
            for (int i = 0; i < 2; i++) {
                const int f = tid + i * 256;
                const int row = f >> 2, c4 = f & 3;
                uint4 h, l;
                split4(g[i], h, l);
                *(uint4*)&Ah[(size_t)row * TS + c4 * 4] = h;
                *(uint4*)&Al[(size_t)row * TS + c4 * 4] = l;
                split4(g[2 + i], h, l);
                *(uint4*)&Bh[(size_t)row * TS + c4 * 4] = h;
                *(uint4*)&Bl[(size_t)row * TS + c4 * 4] = l;
            }
        }
    };

    float c[4][4][4];
#pragma unroll
    for (int i = 0; i < 4; i++)
#pragma unroll
        for (int j = 0; j < 4; j++)
#pragma unroll
            for (int u = 0; u < 4; u++) c[i][j][u] = 0.0f;

    // prologue: chunk 0 into buffer 0
    {
        float4 g[4];
        ldg_chunk(0, g);
        sts_chunk(g, 0);
    }

    for (int ch = 0; ch < nch; ch++) {
        const bool have_next = (ch + 1 < nch);
        float4 g[4];
        if (have_next) ldg_chunk(ch + 1, g);   // gmem latency covered by MMA(c)

        __syncthreads();                        // buf[ch&1] written by all warps

        const float* base = smf + (ch & 1) * BUFF;
        const float* Ah = base;
        const float* Al = base + TILEF;
        const float* Bh = base + 2 * TILEF;
        const float* Bl = base + 3 * TILEF;

        // ---- MMA: 2 k-steps of 8, tf32x3 (R11 order: per am hh,lh,hl) ----
#pragma unroll
        for (int ks = 0; ks < 2; ks++) {
            const int kk = ks * 8;
            uint32_t bh[4][2], bl[4][2];
#pragma unroll
            for (int an = 0; an < 4; an++) {
                const int nb = wn * 32 + an * 8;
                ldfragB(Bh, nb, kk, lane, bh[an]);
                ldfragB(Bl, nb, kk, lane, bl[an]);
            }
#pragma unroll
            for (int am = 0; am < 4; am++) {
                const int mr = wm * 64 + am * 16;
                uint32_t ah[4], al[4];
                ldfragA(Ah, mr, kk, lane, ah);
                ldfragA(Al, mr, kk, lane, al);
#pragma unroll
                for (int an = 0; an < 4; an++) MMA(c[am][an], ah, bh[an]);
#pragma unroll
                for (int an = 0; an < 4; an++) MMA(c[am][an], al, bh[an]);
#pragma unroll
                for (int an = 0; an < 4; an++) MMA(c[am][an], ah, bl[an]);
            }
        }

        // split+STS next chunk into the other buffer (no barrier needed here:
        // nobody reads buf[(ch+1)&1] until the next loop's __syncthreads)
        if (have_next) sts_chunk(g, (ch + 1) & 1);
    }

    // ---- epilogue ----
#pragma unroll
    for (int am = 0; am < 4; am++) {
        const int mr = m0 + wm * 64 + am * 16 + (lane >> 2);
#pragma unroll
        for (int an = 0; an < 4; an++) {
            const int nc = n0 + wn * 32 + an * 8 + (lane & 3) * 2;
            float2 w0 = make_float2(c[am][an][0] * csc, c[am][an][1] * csc);
            float2 w1 = make_float2(c[am][an][2] * csc, c[am][an][3] * csc);
            *(float2*)&Cb[(size_t)mr * LDW + nc]       = w0;
            *(float2*)&Cb[(size_t)(mr + 8) * LDW + nc] = w1;
        }
    }
}

// ---------------------------------------------------------------------------
// Kernel C: mask (col > valid_len[q] -> -1e6) + row softmax over 512 cols.
// ---------------------------------------------------------------------------
__global__ __launch_bounds__(256) void softmax_kernel(float* __restrict__ out)
{
    const int b = blockIdx.y, q0 = blockIdx.x * 32;
    const int tid = threadIdx.x, lane = tid & 31, warp = tid >> 5;
    const int r0 = warp * 4;
    const float* __restrict__ Xb = g_X + (size_t)b * SQ * DV;

    float acc[4][16];
#pragma unroll
    for (int i = 0; i < 4; i++) {
        const float* row = Xb + (size_t)(q0 + r0 + i) * DV;
#pragma unroll
        for (int j = 0; j < 16; j++) acc[i][j] = row[lane + 32 * j];
    }

#pragma unroll
    for (int i = 0; i < 4; i++) {
        const int q = q0 + r0 + i;
        const int vl = g_vl[q];
        float rmax = -3.402823e38f;
#pragma unroll
        for (int j = 0; j < 16; j++) {
            const int cidx = lane + 32 * j;
            float x = acc[i][j];
            if (cidx > vl) x = -1000000.0f;
            acc[i][j] = x;
            rmax = fmaxf(rmax, x);
        }
#pragma unroll
        for (int off = 16; off > 0; off >>= 1)
            rmax = fmaxf(rmax, __shfl_xor_sync(0xFFFFFFFFu, rmax, off));
        float rsum = 0.0f;
#pragma unroll
        for (int j = 0; j < 16; j++) {
            const float e = __expf(acc[i][j] - rmax);
            acc[i][j] = e;
            rsum += e;
        }
#pragma unroll
        for (int off = 16; off > 0; off >>= 1)
            rsum += __shfl_xor_sync(0xFFFFFFFFu, rsum, off);
        const float inv = 1.0f / rsum;
        float* __restrict__ orow = out + (size_t)b * SQ * DV + (size_t)q * DV;
#pragma unroll
        for (int j = 0; j < 16; j++)
            orow[lane + 32 * j] = acc[i][j] * inv;
    }
}

extern "C" void kernel_launch(void* const* d_in, const int* in_sizes, int n_in,
                              void* d_out, int out_size)
{
    const float* K   = (const float*)d_in[0];
    const float* V   = (const float*)d_in[1];
    const float* Q   = (const float*)d_in[2];
    const int*   vlr = (const int*)d_in[3];
    float*       out = (float*)d_out;

    cudaFuncSetAttribute(gemm_mma<1>, cudaFuncAttributeMaxDynamicSharedMemorySize, GEMM_SMEM);
    cudaFuncSetAttribute(gemm_mma<0>, cudaFuncAttributeMaxDynamicSharedMemorySize, GEMM_SMEM);

    normalize_vlen_kernel<<<1, 1024>>>(vlr);

    dim3 gA(DD / 128, DV / 128, NB * KSPLIT);        // (4, 4, 32): partials
    gemm_mma<1><<<gA, 256, GEMM_SMEM>>>(V, K);

    reduce_mt_kernel<<<(NB * DV * DD / 4) / 256, 256>>>();   // 2048 blocks

    dim3 gB(DV / 128, SQ / 128, NB);                 // (4, 16, 8): X[q][v]
    gemm_mma<0><<<gB, 256, GEMM_SMEM>>>(Q, nullptr);

    dim3 gC(SQ / 32, NB);                            // (64, 8)
    softmax_kernel<<<gC, 256>>>(out);
}